// round 1
// baseline (speedup 1.0000x reference)
#include <cuda_runtime.h>
#include <math.h>

#define BB 64
#define NN 128
#define LL 64
#define DD 768
#define NEGV (-9e9f)

// Scratch (no cudaMalloc allowed): pairwise score matrix + diagonal-tile
// row-softmax probabilities stored transposed [b][l][n] for the i2s GEMM.
__device__ float g_S[BB * BB];
__device__ float g_P[BB * LL * NN];

// ---------------------------------------------------------------------------
// packed f32x2 helpers (FFMA2 — 2x fp32 FMA throughput on sm_103a)
// ---------------------------------------------------------------------------
__device__ __forceinline__ void ffma2(unsigned long long &c,
                                      unsigned long long a,
                                      unsigned long long b) {
    asm("fma.rn.f32x2 %0, %1, %2, %0;" : "+l"(c) : "l"(a), "l"(b));
}
__device__ __forceinline__ unsigned long long pack2(float x, float y) {
    unsigned long long r;
    asm("mov.b64 %0, {%1, %2};" : "=l"(r) : "f"(x), "f"(y));
    return r;
}
__device__ __forceinline__ float2 unpack2(unsigned long long v) {
    float2 f;
    asm("mov.b64 {%0, %1}, %2;" : "=f"(f.x), "=f"(f.y) : "l"(v));
    return f;
}

// ---------------------------------------------------------------------------
// Kernel A: one (i,j) pair per block. Fused 128x64x768 GEMM (f32x2, SW128
// SMEM) + masked row/col softmax + score reduction. Diagonal blocks also
// emit the row-softmax probabilities (token_scores softmax) to g_P.
// ---------------------------------------------------------------------------
__global__ __launch_bounds__(256, 2)
void ground_kernel(const float* __restrict__ text, const float* __restrict__ img,
                   const int* __restrict__ tmask, const int* __restrict__ imask)
{
    const int i = blockIdx.y;   // text batch
    const int j = blockIdx.x;   // image batch

    __shared__ __align__(16) char s_u[33280];  // GEMM stage (24KB) / att tile (33.3KB)
    __shared__ int tm_s[NN];
    __shared__ int im_s[LL];
    __shared__ float red_s[8];

    char*  Abase = s_u;           // A stage: 128 rows x 128B (SW128)
    char*  Bbase = s_u + 16384;   // B stage:  64 rows x 128B (SW128)
    float* att_s = (float*)s_u;   // att tile [128][65] (reuses GEMM stage)

    const int t  = threadIdx.x;
    const int tx = t & 15;        // col group (4 cols, stride 16)
    const int ty = t >> 4;        // row group (8 rows, stride 16)

    if (t < NN) tm_s[t] = tmask[i * NN + t];
    if (t < LL) im_s[t] = imask[j * LL + t];

    const float* Tg = text + (size_t)i * NN * DD;
    const float* Ig = img  + (size_t)j * LL * DD;

    unsigned long long acc[8][4];
#pragma unroll
    for (int r = 0; r < 8; r++)
#pragma unroll
        for (int c = 0; c < 4; c++) acc[r][c] = 0ull;

    for (int kc = 0; kc < DD; kc += 32) {
        // stage A chunk: 128x32 f32, SW128-swizzled 128B rows
#pragma unroll
        for (int q = 0; q < 4; q++) {
            int f = t + q * 256;
            int r = f >> 3, k4 = f & 7;
            float4 v = *(const float4*)(Tg + r * DD + kc + k4 * 4);
            int off = r * 128 + k4 * 16;
            off ^= (off >> 3) & 0x70;
            *(float4*)(Abase + off) = v;
        }
        // stage B chunk: 64x32 f32
#pragma unroll
        for (int q = 0; q < 2; q++) {
            int f = t + q * 256;
            int r = f >> 3, k4 = f & 7;
            float4 v = *(const float4*)(Ig + r * DD + kc + k4 * 4);
            int off = r * 128 + k4 * 16;
            off ^= (off >> 3) & 0x70;
            *(float4*)(Bbase + off) = v;
        }
        __syncthreads();

#pragma unroll
        for (int k2 = 0; k2 < 16; k2++) {          // k-pairs within chunk
            unsigned long long a[8], b[4];
#pragma unroll
            for (int rr = 0; rr < 8; rr++) {
                int row = ty + rr * 16;
                int off = row * 128 + ((k2 * 8) ^ ((row & 7) << 4));
                a[rr] = *(const unsigned long long*)(Abase + off);
            }
#pragma unroll
            for (int cc = 0; cc < 4; cc++) {
                int col = tx + cc * 16;
                int off = col * 128 + ((k2 * 8) ^ ((col & 7) << 4));
                b[cc] = *(const unsigned long long*)(Bbase + off);
            }
#pragma unroll
            for (int rr = 0; rr < 8; rr++)
#pragma unroll
                for (int cc = 0; cc < 4; cc++)
                    ffma2(acc[rr][cc], a[rr], b[cc]);
        }
        __syncthreads();
    }

    // masked att tile into SMEM: att = (mask && dot!=0) ? dot : NEG
#pragma unroll
    for (int rr = 0; rr < 8; rr++) {
        int row = ty + rr * 16;
        int tm  = tm_s[row];
#pragma unroll
        for (int cc = 0; cc < 4; cc++) {
            int col = tx + cc * 16;
            float2 p = unpack2(acc[rr][cc]);
            float dot = p.x + p.y;   // even-k half + odd-k half
            float v = (tm && im_s[col] && dot != 0.f) ? dot : NEGV;
            att_s[row * 65 + col] = v;
        }
    }
    __syncthreads();

    float local = 0.f;

    // ---- row softmax over L (score1) + diag prob emission -----------------
    if (t < NN) {
        const int row = t;
        const float* ar = att_s + row * 65;
        float mx = -INFINITY;
#pragma unroll 8
        for (int l = 0; l < LL; l++) mx = fmaxf(mx, ar[l]);
        float Z = 0.f;
#pragma unroll 8
        for (int l = 0; l < LL; l++) Z += __expf(ar[l] - mx);
        float inv = __frcp_rn(Z);
        const int tm = tm_s[row];
        const bool diag = (i == j);
        float* Pp = g_P + (size_t)i * LL * NN + row;   // [l][n], stride NN
        float s1 = 0.f;
#pragma unroll 8
        for (int l = 0; l < LL; l++) {
            float a = ar[l];
            float p = __expf(a - mx) * inv;
            if (diag) Pp[l * NN] = p;            // token-score softmax (unmasked)
            if (tm && im_s[l]) s1 += p * a;      // aw_first * mask * att
        }
        local += s1;
    }

    // ---- col softmax over N (score2) --------------------------------------
    if (t < LL) {
        const int col = t;
        const float* ac = att_s + col;
        float mx = -INFINITY;
#pragma unroll 8
        for (int n = 0; n < NN; n++) mx = fmaxf(mx, ac[n * 65]);
        float Z = 0.f;
#pragma unroll 8
        for (int n = 0; n < NN; n++) Z += __expf(ac[n * 65] - mx);
        float inv = __frcp_rn(Z);
        const int im = im_s[col];
        float s2 = 0.f;
#pragma unroll 8
        for (int n = 0; n < NN; n++) {
            float a = ac[n * 65];
            float p = __expf(a - mx) * inv;
            if (im && tm_s[n]) s2 += p * a;      // aw_second * mask * att
        }
        local += s2;
    }

    // ---- deterministic block reduce → S[i][j] ------------------------------
#pragma unroll
    for (int o = 16; o > 0; o >>= 1)
        local += __shfl_xor_sync(0xffffffffu, local, o);
    if ((t & 31) == 0) red_s[t >> 5] = local;
    __syncthreads();
    if (t == 0) {
        float s = 0.f;
#pragma unroll
        for (int w = 0; w < 8; w++) s += red_s[w];
        g_S[i * BB + j] = s * (1.f / 128.f);     // mean over n
    }
}

// ---------------------------------------------------------------------------
// Kernel B: contrastive loss from S (row + column log-softmax diagonals)
// ---------------------------------------------------------------------------
__global__ void loss_kernel(float* __restrict__ out)
{
    __shared__ float Ss[BB * BB];
    __shared__ float part[BB];
    const int t = threadIdx.x;                    // 64 threads
    for (int k = t; k < BB * BB; k += BB) Ss[k] = g_S[k];
    __syncthreads();

    float mx = -INFINITY;
    for (int c = 0; c < BB; c++) mx = fmaxf(mx, Ss[t * BB + c]);
    float Z = 0.f;
    for (int c = 0; c < BB; c++) Z += expf(Ss[t * BB + c] - mx);
    float lse_r = mx + logf(Z);

    float mc = -INFINITY;
    for (int r = 0; r < BB; r++) mc = fmaxf(mc, Ss[r * BB + t]);
    float Zc = 0.f;
    for (int r = 0; r < BB; r++) Zc += expf(Ss[r * BB + t] - mc);
    float lse_c = mc + logf(Zc);

    float d = Ss[t * BB + t];
    part[t] = (d - lse_r) + (d - lse_c);
    __syncthreads();
    if (t == 0) {
        float s = 0.f;
        for (int k = 0; k < BB; k++) s += part[k];
        out[0] = -s / (float)BB;
    }
}

// ---------------------------------------------------------------------------
// Kernel C: text_emb_i2s[b] = P[b] @ V[b]   (P: [n][l] probs, stored [l][n])
// grid (6 d-chunks of 128, 64 batches). f32x2 paired over n.
// ---------------------------------------------------------------------------
__global__ __launch_bounds__(256)
void i2s_kernel(const float* __restrict__ img, float* __restrict__ out)
{
    extern __shared__ float cs[];
    float* V_s = cs;              // [64][128] d-chunk of V
    float* P_s = cs + 64 * 128;   // [64][128] = [l][n]
    const int b  = blockIdx.y;
    const int dc = blockIdx.x;    // 0..5
    const int t  = threadIdx.x;
    const int dq = t & 31;        // 4 d's: dq + {0,32,64,96}
    const int ng = t >> 5;        // 8 n-pairs: ng*8 + nn

    const float* Vg = img + (size_t)b * LL * DD + dc * 128;
#pragma unroll
    for (int q = 0; q < 8; q++) {
        int f = t + q * 256;
        int l = f >> 5, c4 = f & 31;
        *(float4*)&V_s[l * 128 + c4 * 4] = *(const float4*)(Vg + l * DD + c4 * 4);
    }
    const float* Pgp = g_P + (size_t)b * LL * NN;
#pragma unroll
    for (int q = 0; q < 8; q++) {
        int f = t + q * 256;
        *(float4*)&P_s[f * 4] = *(const float4*)(Pgp + f * 4);
    }
    __syncthreads();

    unsigned long long acc[8][4];
#pragma unroll
    for (int nn = 0; nn < 8; nn++)
#pragma unroll
        for (int dd = 0; dd < 4; dd++) acc[nn][dd] = 0ull;

#pragma unroll 4
    for (int l = 0; l < LL; l++) {
        float v0 = V_s[l * 128 + dq];
        float v1 = V_s[l * 128 + dq + 32];
        float v2 = V_s[l * 128 + dq + 64];
        float v3 = V_s[l * 128 + dq + 96];
        unsigned long long bv0 = pack2(v0, v0);
        unsigned long long bv1 = pack2(v1, v1);
        unsigned long long bv2 = pack2(v2, v2);
        unsigned long long bv3 = pack2(v3, v3);
#pragma unroll
        for (int nn = 0; nn < 8; nn++) {
            int np = ng * 8 + nn;
            unsigned long long a = *(const unsigned long long*)&P_s[l * 128 + np * 2];
            ffma2(acc[nn][0], a, bv0);
            ffma2(acc[nn][1], a, bv1);
            ffma2(acc[nn][2], a, bv2);
            ffma2(acc[nn][3], a, bv3);
        }
    }

    // out is offset by 1 float (loss at [0]) → scalar stores, coalesced per dd
    float* ob = out + 1 + (size_t)b * NN * DD + dc * 128;
#pragma unroll
    for (int nn = 0; nn < 8; nn++) {
        int n0 = (ng * 8 + nn) * 2;
#pragma unroll
        for (int dd = 0; dd < 4; dd++) {
            float2 v = unpack2(acc[nn][dd]);
            ob[(size_t)n0 * DD + dd * 32 + dq]       = v.x;
            ob[(size_t)(n0 + 1) * DD + dd * 32 + dq] = v.y;
        }
    }
}

// ---------------------------------------------------------------------------
extern "C" void kernel_launch(void* const* d_in, const int* in_sizes, int n_in,
                              void* d_out, int out_size)
{
    (void)in_sizes; (void)n_in; (void)out_size;
    const float* text = (const float*)d_in[0];
    const float* img  = (const float*)d_in[1];
    const int*  tmask = (const int*)d_in[2];
    const int*  imask = (const int*)d_in[3];
    float* out = (float*)d_out;

    cudaFuncSetAttribute(i2s_kernel, cudaFuncAttributeMaxDynamicSharedMemorySize, 65536);

    dim3 g(BB, BB);
    ground_kernel<<<g, 256>>>(text, img, tmask, imask);
    loss_kernel<<<1, 64>>>(out);
    i2s_kernel<<<dim3(6, BB), 256, 65536>>>(img, out);
}

// round 5
// speedup vs baseline: 2.3017x; 2.3017x over previous
#include <cuda_runtime.h>
#include <cuda_bf16.h>
#include <math.h>
#include <stdint.h>

#define BB 64
#define NN 128
#define LL 64
#define DD 768
#define NEGV (-9e9f)
#define NCH 12            // K chunks of 64
#define NEGC NEGV

// -------- device scratch (no cudaMalloc allowed) ---------------------------
// bf16 hi/lo splits, PRE-SWIZZLED (SW128 within 128B rows) chunked layout:
// A: [i][c][row 0..127][64 bf16], B: [j][c][row 0..63][64 bf16]
__device__ __nv_bfloat16 g_tAh[BB * NN * DD];
__device__ __nv_bfloat16 g_tAl[BB * NN * DD];
__device__ __nv_bfloat16 g_tBh[BB * LL * DD];
__device__ __nv_bfloat16 g_tBl[BB * LL * DD];
__device__ float g_S[BB * BB];
__device__ float g_P[BB * LL * NN];

// -------- helpers ----------------------------------------------------------
__device__ __forceinline__ uint32_t smem_u32(const void* p) {
    uint32_t a;
    asm("{ .reg .u64 t; cvta.to.shared.u64 t, %1; cvt.u32.u64 %0, t; }" : "=r"(a) : "l"(p));
    return a;
}
__device__ __forceinline__ void cp16(uint32_t dst, const void* src) {
    unsigned long long g = (unsigned long long)__cvta_generic_to_global(src);
    asm volatile("cp.async.cg.shared.global [%0], [%1], 16;" :: "r"(dst), "l"(g));
}
#define CP_COMMIT() asm volatile("cp.async.commit_group;" ::: "memory")

#define LDSM_X4(r0, r1, r2, r3, a) \
    asm volatile("ldmatrix.sync.aligned.m8n8.x4.shared.b16 {%0,%1,%2,%3}, [%4];" \
                 : "=r"(r0), "=r"(r1), "=r"(r2), "=r"(r3) : "r"(a))

#define MMA_BF16(d, a, b) \
    asm volatile("mma.sync.aligned.m16n8k16.row.col.f32.bf16.bf16.f32 " \
                 "{%0,%1,%2,%3},{%4,%5,%6,%7},{%8,%9},{%0,%1,%2,%3};" \
                 : "+f"((d)[0]), "+f"((d)[1]), "+f"((d)[2]), "+f"((d)[3]) \
                 : "r"((a)[0]), "r"((a)[1]), "r"((a)[2]), "r"((a)[3]), \
                   "r"((b)[0]), "r"((b)[1]))

// FMA-pipe exp (no MUFU): exp(x), x<=0, poly exp2 deg-6
__device__ __forceinline__ float fexp(float x) {
    float t = fmaxf(x * 1.44269504089f, -126.f);
    int   ni = __float2int_rn(t);
    float f  = t - (float)ni;
    float p = 1.54653240e-4f;
    p = fmaf(p, f, 1.33335581e-3f);
    p = fmaf(p, f, 9.61812910e-3f);
    p = fmaf(p, f, 5.55041087e-2f);
    p = fmaf(p, f, 2.40226507e-1f);
    p = fmaf(p, f, 6.93147182e-1f);
    p = fmaf(p, f, 1.0f);
    return __int_as_float(__float_as_int(p) + (ni << 23));
}

// f32x2 helpers (i2s kernel)
__device__ __forceinline__ void ffma2(unsigned long long &c, unsigned long long a,
                                      unsigned long long b) {
    asm("fma.rn.f32x2 %0, %1, %2, %0;" : "+l"(c) : "l"(a), "l"(b));
}
__device__ __forceinline__ unsigned long long pack2(float x, float y) {
    unsigned long long r;
    asm("mov.b64 %0, {%1, %2};" : "=l"(r) : "f"(x), "f"(y));
    return r;
}
__device__ __forceinline__ float2 unpack2(unsigned long long v) {
    float2 f;
    asm("mov.b64 {%0, %1}, %2;" : "=f"(f.x), "=f"(f.y) : "l"(v));
    return f;
}

// ---------------------------------------------------------------------------
// Kernel 0: f32 -> bf16 hi/lo split, pre-swizzled chunk layout.
// swizzle (bf16 elems within 64-wide row): kin ^= (row&7)<<3
// ---------------------------------------------------------------------------
__global__ void conv_kernel(const float* __restrict__ text, const float* __restrict__ img)
{
    const int TXT = BB * NN * DD;
    int idx = blockIdx.x * 256 + threadIdx.x;
    if (idx < TXT) {
        float v = text[idx];
        __nv_bfloat16 hi = __float2bfloat16(v);
        __nv_bfloat16 lo = __float2bfloat16(v - __bfloat162float(hi));
        int d = idx % DD, n = (idx / DD) % NN, i = idx / (NN * DD);
        int c = d >> 6, kin = d & 63;
        int off = ((i * NCH + c) * NN + n) * 64 + (kin ^ ((n & 7) << 3));
        g_tAh[off] = hi; g_tAl[off] = lo;
    } else {
        int x = idx - TXT;
        float v = img[x];
        __nv_bfloat16 hi = __float2bfloat16(v);
        __nv_bfloat16 lo = __float2bfloat16(v - __bfloat162float(hi));
        int d = x % DD, l = (x / DD) % LL, j = x / (LL * DD);
        int c = d >> 6, kin = d & 63;
        int off = ((j * NCH + c) * LL + l) * 64 + (kin ^ ((l & 7) << 3));
        g_tBh[off] = hi; g_tBl[off] = lo;
    }
}

// ---------------------------------------------------------------------------
// cp.async staging of one K-chunk (64 k) into SMEM buffer B0:
//  [0,16K)  A hi  (128 rows x 128B)   [16K,32K) A lo
//  [32K,48K) B hi (128 n-rows x 128B) [48K,64K) B lo
// Source is pre-swizzled -> purely linear 16B copies.
// ---------------------------------------------------------------------------
__device__ __forceinline__ void issue_chunk(uint32_t B0, int i, int jg, int c, int t)
{
    const __nv_bfloat16* Ah = g_tAh + (size_t)(i * NCH + c) * (NN * 64);
    const __nv_bfloat16* Al = g_tAl + (size_t)(i * NCH + c) * (NN * 64);
#pragma unroll
    for (int q = 0; q < 4; q++) {
        int idx = t + q * 256;
        cp16(B0 + idx * 16, Ah + idx * 8);
        cp16(B0 + 16384 + idx * 16, Al + idx * 8);
    }
#pragma unroll
    for (int q = 0; q < 4; q++) {
        int idx = t + q * 256;                  // 0..1023, n-row = idx>>3
        int jj = idx >> 9;                      // which image batch half
        size_t so = (size_t)((jg * 2 + jj) * NCH + c) * (LL * 64) + (idx & 511) * 8;
        cp16(B0 + 32768 + idx * 16, g_tBh + so);
        cp16(B0 + 49152 + idx * 16, g_tBl + so);
    }
}

// ---------------------------------------------------------------------------
// Kernel A: bf16 mma.sync 3x GEMM (M=128, N=128, K=768) + fused masked
// softmax epilogue. Grid (32 j-groups of 2, 64 i). 256 threads, warps 2x4.
// ---------------------------------------------------------------------------
__global__ __launch_bounds__(256, 1)
void ground3(const int* __restrict__ tmask, const int* __restrict__ imask)
{
    extern __shared__ __align__(16) char dsm[];   // 131072: 2 x 64KB stage / att
    __shared__ int   tm_s[NN];
    __shared__ int   im_s[NN];
    __shared__ float row_s1[NN];
    __shared__ float col_s2[LL];

    const int i  = blockIdx.y;
    const int jg = blockIdx.x;
    const int t  = threadIdx.x;
    const int wid = t >> 5, lane = t & 31;
    const uint32_t sb = smem_u32(dsm);

    if (t < NN) {
        tm_s[t] = tmask[i * NN + t];
        im_s[t] = imask[(jg * 2 + (t >> 6)) * LL + (t & 63)];
    }

    const int m0 = (wid >> 2) * 64;
    const int n0 = (wid & 3) * 32;

    // ldmatrix lane address precompute (swizzle key depends only on lane bits)
    const int lr   = lane & 15, half = lane >> 4;          // A mapping
    const int xorA = (lr & 7) << 4;
    const int qb   = lane >> 3, bl = lane & 7;             // B mapping
    const int xorB = bl << 4;
    const int rowB_off = ((qb & 1) << 3) + bl;             // within 16-n group
    const int kB_half  = (qb >> 1) << 4;

    float acc[4][4][4];
#pragma unroll
    for (int a = 0; a < 4; a++)
#pragma unroll
        for (int b = 0; b < 4; b++)
#pragma unroll
            for (int r = 0; r < 4; r++) acc[a][b][r] = 0.f;

    issue_chunk(sb, i, jg, 0, t);
    CP_COMMIT();

    for (int c = 0; c < NCH; c++) {
        const uint32_t SB = sb + (c & 1) * 65536;
        if (c + 1 < NCH) {
            issue_chunk(sb + ((c + 1) & 1) * 65536, i, jg, c + 1, t);
            CP_COMMIT();
            asm volatile("cp.async.wait_group 1;" ::: "memory");
        } else {
            asm volatile("cp.async.wait_group 0;" ::: "memory");
        }
        __syncthreads();

        const uint32_t Ah = SB, Al = SB + 16384, Bh = SB + 32768, Bl = SB + 49152;
#pragma unroll
        for (int s = 0; s < 4; s++) {
            const int kb = s * 32;
            const int kaA = (kb | (half << 4)) ^ xorA;
            const int kaB = (kb | kB_half) ^ xorB;

            uint32_t ah[4][4], al[4][4], bh[4][2], blr[4][2];
#pragma unroll
            for (int mf = 0; mf < 4; mf++) {
                int row = m0 + mf * 16 + lr;
                uint32_t ad = Ah + row * 128 + kaA;
                LDSM_X4(ah[mf][0], ah[mf][1], ah[mf][2], ah[mf][3], ad);
                uint32_t ad2 = Al + row * 128 + kaA;
                LDSM_X4(al[mf][0], al[mf][1], al[mf][2], al[mf][3], ad2);
            }
#pragma unroll
            for (int g2 = 0; g2 < 2; g2++) {
                int rowb = n0 + g2 * 16 + rowB_off;
                uint32_t bd = Bh + rowb * 128 + kaB;
                uint32_t r0, r1, r2, r3;
                LDSM_X4(r0, r1, r2, r3, bd);
                bh[g2 * 2][0] = r0; bh[g2 * 2 + 1][0] = r1;
                bh[g2 * 2][1] = r2; bh[g2 * 2 + 1][1] = r3;
                uint32_t bd2 = Bl + rowb * 128 + kaB;
                LDSM_X4(r0, r1, r2, r3, bd2);
                blr[g2 * 2][0] = r0; blr[g2 * 2 + 1][0] = r1;
                blr[g2 * 2][1] = r2; blr[g2 * 2 + 1][1] = r3;
            }
#pragma unroll
            for (int mf = 0; mf < 4; mf++)
#pragma unroll
                for (int nf = 0; nf < 4; nf++) {
                    MMA_BF16(acc[mf][nf], ah[mf], bh[nf]);
                    MMA_BF16(acc[mf][nf], ah[mf], blr[nf]);
                    MMA_BF16(acc[mf][nf], al[mf], bh[nf]);
                }
        }
        __syncthreads();   // all warps done with SB before it is re-staged
    }

    // ---- masked att tile -> SMEM (reuse stage buffers), pitch 132 ---------
    float* att = (float*)dsm;
    const int gr = lane >> 2, cp = (lane & 3) * 2;
#pragma unroll
    for (int mf = 0; mf < 4; mf++)
#pragma unroll
        for (int nf = 0; nf < 4; nf++) {
            int row = m0 + mf * 16 + gr;
            int col = n0 + nf * 8 + cp;
            float* d = acc[mf][nf];
            int tmr0 = tm_s[row], tmr1 = tm_s[row + 8];
            int imc0 = im_s[col], imc1 = im_s[col + 1];
            float2 v0, v1;
            v0.x = (tmr0 && imc0 && d[0] != 0.f) ? d[0] : NEGC;
            v0.y = (tmr0 && imc1 && d[1] != 0.f) ? d[1] : NEGC;
            v1.x = (tmr1 && imc0 && d[2] != 0.f) ? d[2] : NEGC;
            v1.y = (tmr1 && imc1 && d[3] != 0.f) ? d[3] : NEGC;
            *(float2*)&att[row * 132 + col]       = v0;
            *(float2*)&att[(row + 8) * 132 + col] = v1;
        }
    __syncthreads();

    // ---- softmax epilogue, per image batch jj in {0,1} --------------------
    for (int jj = 0; jj < 2; jj++) {
        const int j = jg * 2 + jj;

        if (t < NN) {   // row softmax over L=64
            const float* ar = att + t * 132 + jj * 64;
            float a[64];
            float mx = -INFINITY;
#pragma unroll 8
            for (int c2 = 0; c2 < 64; c2++) { a[c2] = ar[c2]; mx = fmaxf(mx, a[c2]); }
            float Z = 0.f, num = 0.f;
            const int tm = tm_s[t];
#pragma unroll 8
            for (int c2 = 0; c2 < 64; c2++) {
                float e = fexp(a[c2] - mx);
                Z += e;
                num += (tm && im_s[jj * 64 + c2]) ? e * a[c2] : 0.f;
            }
            float inv = __frcp_rn(Z);
            row_s1[t] = num * inv;
            if (j == i) {   // diag: token-score softmax probs, transposed [l][n]
                float* Pp = g_P + (size_t)i * LL * NN + t;
#pragma unroll 8
                for (int c2 = 0; c2 < 64; c2++)
                    Pp[c2 * NN] = fexp(a[c2] - mx) * inv;
            }
        }
        __syncthreads();

        {   // col softmax over N=128: 4 threads per column
            const int cc = t >> 2, seg = t & 3;
            const int im = im_s[jj * 64 + cc];
            const float* ac = att + jj * 64 + cc;
            float mx = -INFINITY;
#pragma unroll 8
            for (int r = seg * 32; r < seg * 32 + 32; r++) mx = fmaxf(mx, ac[r * 132]);
            mx = fmaxf(mx, __shfl_xor_sync(~0u, mx, 1));
            mx = fmaxf(mx, __shfl_xor_sync(~0u, mx, 2));
            float Z = 0.f, num = 0.f;
#pragma unroll 8
            for (int r = seg * 32; r < seg * 32 + 32; r++) {
                float av = ac[r * 132];
                float e = fexp(av - mx);
                Z += e;
                num += (im && tm_s[r]) ? e * av : 0.f;
            }
            Z += __shfl_xor_sync(~0u, Z, 1);  Z += __shfl_xor_sync(~0u, Z, 2);
            num += __shfl_xor_sync(~0u, num, 1); num += __shfl_xor_sync(~0u, num, 2);
            if (seg == 0) col_s2[cc] = num * __frcp_rn(Z);
        }
        __syncthreads();

        if (t < 32) {
            float s = row_s1[t * 4] + row_s1[t * 4 + 1] + row_s1[t * 4 + 2] + row_s1[t * 4 + 3]
                    + col_s2[t * 2] + col_s2[t * 2 + 1];
#pragma unroll
            for (int o = 16; o > 0; o >>= 1) s += __shfl_xor_sync(~0u, s, o);
            if (t == 0) g_S[i * BB + j] = s * (1.f / 128.f);
        }
        __syncthreads();
    }
}

// ---------------------------------------------------------------------------
// Kernel B: contrastive loss from S
// ---------------------------------------------------------------------------
__global__ void loss_kernel(float* __restrict__ out)
{
    __shared__ float Ss[BB * BB];
    __shared__ float part[BB];
    const int t = threadIdx.x;  // 64
    for (int k = t; k < BB * BB; k += BB) Ss[k] = g_S[k];
    __syncthreads();
    float mx = -INFINITY;
    for (int c = 0; c < BB; c++) mx = fmaxf(mx, Ss[t * BB + c]);
    float Z = 0.f;
    for (int c = 0; c < BB; c++) Z += expf(Ss[t * BB + c] - mx);
    float lse_r = mx + logf(Z);
    float mc = -INFINITY;
    for (int r = 0; r < BB; r++) mc = fmaxf(mc, Ss[r * BB + t]);
    float Zc = 0.f;
    for (int r = 0; r < BB; r++) Zc += expf(Ss[r * BB + t] - mc);
    float lse_c = mc + logf(Zc);
    float d = Ss[t * BB + t];
    part[t] = (d - lse_r) + (d - lse_c);
    __syncthreads();
    if (t == 0) {
        float s = 0.f;
        for (int k = 0; k < BB; k++) s += part[k];
        out[0] = -s / (float)BB;
    }
}

// ---------------------------------------------------------------------------
// Kernel C: text_emb_i2s[b] = P[b] @ V[b]  (P stored [l][n])
// ---------------------------------------------------------------------------
__global__ __launch_bounds__(256)
void i2s_kernel(const float* __restrict__ img, float* __restrict__ out)
{
    extern __shared__ float cs[];
    float* V_s = cs;
    float* P_s = cs + 64 * 128;
    const int b = blockIdx.y, dc = blockIdx.x, t = threadIdx.x;
    const int dq = t & 31, ng = t >> 5;

    const float* Vg = img + (size_t)b * LL * DD + dc * 128;
#pragma unroll
    for (int q = 0; q < 8; q++) {
        int f = t + q * 256;
        int l = f >> 5, c4 = f & 31;
        *(float4*)&V_s[l * 128 + c4 * 4] = *(const float4*)(Vg + l * DD + c4 * 4);
    }
    const float* Pgp = g_P + (size_t)b * LL * NN;
#pragma unroll
    for (int q = 0; q < 8; q++) {
        int f = t + q * 256;
        *(float4*)&P_s[f * 4] = *(const float4*)(Pgp + f * 4);
    }
    __syncthreads();

    unsigned long long acc[8][4];
#pragma unroll
    for (int nn = 0; nn < 8; nn++)
#pragma unroll
        for (int dd = 0; dd < 4; dd++) acc[nn][dd] = 0ull;

#pragma unroll 4
    for (int l = 0; l < LL; l++) {
        float v0 = V_s[l * 128 + dq];
        float v1 = V_s[l * 128 + dq + 32];
        float v2 = V_s[l * 128 + dq + 64];
        float v3 = V_s[l * 128 + dq + 96];
        unsigned long long bv0 = pack2(v0, v0), bv1 = pack2(v1, v1);
        unsigned long long bv2 = pack2(v2, v2), bv3 = pack2(v3, v3);
#pragma unroll
        for (int nn = 0; nn < 8; nn++) {
            int np = ng * 8 + nn;
            unsigned long long a = *(const unsigned long long*)&P_s[l * 128 + np * 2];
            ffma2(acc[nn][0], a, bv0);
            ffma2(acc[nn][1], a, bv1);
            ffma2(acc[nn][2], a, bv2);
            ffma2(acc[nn][3], a, bv3);
        }
    }
    float* ob = out + 1 + (size_t)b * NN * DD + dc * 128;
#pragma unroll
    for (int nn = 0; nn < 8; nn++) {
        int n0 = (ng * 8 + nn) * 2;
#pragma unroll
        for (int dd = 0; dd < 4; dd++) {
            float2 v = unpack2(acc[nn][dd]);
            ob[(size_t)n0 * DD + dd * 32 + dq]       = v.x;
            ob[(size_t)(n0 + 1) * DD + dd * 32 + dq] = v.y;
        }
    }
}

// ---------------------------------------------------------------------------
extern "C" void kernel_launch(void* const* d_in, const int* in_sizes, int n_in,
                              void* d_out, int out_size)
{
    (void)in_sizes; (void)n_in; (void)out_size;
    const float* text = (const float*)d_in[0];
    const float* img  = (const float*)d_in[1];
    const int* tmask  = (const int*)d_in[2];
    const int* imask  = (const int*)d_in[3];
    float* out = (float*)d_out;

    cudaFuncSetAttribute(ground3, cudaFuncAttributeMaxDynamicSharedMemorySize, 131072);
    cudaFuncSetAttribute(i2s_kernel, cudaFuncAttributeMaxDynamicSharedMemorySize, 65536);

    conv_kernel<<<(BB * NN * DD + BB * LL * DD) / 256, 256>>>(text, img);
    ground3<<<dim3(32, BB), 256, 131072>>>(tmask, imask);
    loss_kernel<<<1, 64>>>(out);
    i2s_kernel<<<dim3(6, BB), 256, 65536>>>(img, out);
}